// round 4
// baseline (speedup 1.0000x reference)
#include <cuda_runtime.h>

// PeptidePocketConvLayer — GB300 sm_103a
//
// Inputs (metadata order):
//   d_in[0]: peptide_encoding  f32 [B, 15, 20]
//   d_in[1]: pocket_encoding   i32 [B, 34]
//   d_in[2]: kernel            f32 [20, 9]
// Output: f32 [B, 34, 28]
//
// Structure exploited:
//  - pocket mask is periodic with period 9 -> only 9 distinct aggregates/batch
//  - peptide rows 9..14 are never referenced by any pocket
//  - full conv done with a zero-padded shared row (logical indices -8..27)

#define NPOCK      34
#define OUTW       28
#define OUT_F4     238          // 34*28/4 float4 per batch
#define PEP_STRIDE 300          // 15*20 floats per batch
#define AGG_STRIDE 36           // padded row: logical a-index -8..27

__global__ __launch_bounds__(256, 8)
void pep_pocket_conv_kernel(const float* __restrict__ pep,
                            const int*   __restrict__ pock,
                            const float* __restrict__ ker,
                            float*       __restrict__ out)
{
    __shared__ __align__(16) float sPep[180];          // rows 0..8, 20 each
    __shared__ __align__(16) float sAgg[9 * AGG_STRIDE];
    __shared__ float sFilt[NPOCK * 9];                 // per-pocket filter rows
    __shared__ int   sId[NPOCK];

    const int b = blockIdx.x;
    const int t = threadIdx.x;

    // ---- stage inputs (issue pocket ids first: filter gather depends on them) ----
    if (t < NPOCK) {
        sId[t] = pock[(size_t)b * NPOCK + t];
    }
    if (t < 45) {
        // 720 contiguous bytes: peptide rows 0..8 only
        ((float4*)sPep)[t] =
            __ldg((const float4*)(pep + (size_t)b * PEP_STRIDE) + t);
    }
    // zero the padded aggregate buffer (padding regions must be 0)
    for (int i = t; i < 9 * AGG_STRIDE; i += 256) sAgg[i] = 0.0f;
    __syncthreads();

    // ---- gather filters: sFilt[p*9 + j] = kernel[id[p]][j] (L1/L2 resident) ----
    // 306 entries > 256 threads -> strided loop (round-1 bug was a bad guard here).
    for (int i = t; i < NPOCK * 9; i += 256) {
        sFilt[i] = __ldg(ker + sId[i / 9] * 9 + (i % 9));
    }

    // ---- compute 9 distinct aggregates (pocket mask period 9) ----
    // q: positions = {q%9, 3*(q%3)} dedup'd:
    //   q0:{0} q1:{1,3} q2:{2,6} q3:{0,3} q4:{3,4} q5:{5,6} q6:{0,6} q7:{3,7} q8:{6,8}
    if (t < 180) {
        const signed char J0[9] = { 0, 1, 2, 0, 3, 5, 0, 3, 6 };
        const signed char J1[9] = {-1, 3, 6, 3, 4, 6, 6, 7, 8 };
        int q = t / 20, a = t % 20;
        float v = sPep[(int)J0[q] * 20 + a];
        int j1 = J1[q];
        if (j1 >= 0) v += sPep[j1 * 20 + a];
        sAgg[q * AGG_STRIDE + 8 + a] = v;   // logical index a at offset a+8
    }
    __syncthreads();

    // ---- convolution: 238 threads, each one float4 of output ----
    if (t < OUT_F4) {
        const int p  = t / 7;           // pocket 0..33
        const int k0 = (t % 7) * 4;     // output k base 0,4,...,24
        const int q  = p % 9;

        // filter row into registers (mostly broadcast within a warp)
        float f[9];
        #pragma unroll
        for (int j = 0; j < 9; ++j) f[j] = sFilt[p * 9 + j];

        // a[0..11] = padded aggregate, logical indices k0-8 .. k0+3
        const float* rowp = &sAgg[q * AGG_STRIDE + k0];   // (k0-8)+8 = k0, 16B aligned
        float4 a0 = *(const float4*)(rowp + 0);
        float4 a1 = *(const float4*)(rowp + 4);
        float4 a2 = *(const float4*)(rowp + 8);
        float a[12] = { a0.x, a0.y, a0.z, a0.w,
                        a1.x, a1.y, a1.z, a1.w,
                        a2.x, a2.y, a2.z, a2.w };

        float o0 = 0.f, o1 = 0.f, o2 = 0.f, o3 = 0.f;
        #pragma unroll
        for (int j = 0; j < 9; ++j) {
            // out[k] = sum_j f[j] * a_logical[k - j]; reg index = (c)+8-j
            o0 = fmaf(f[j], a[8  - j], o0);
            o1 = fmaf(f[j], a[9  - j], o1);
            o2 = fmaf(f[j], a[10 - j], o2);
            o3 = fmaf(f[j], a[11 - j], o3);
        }

        ((float4*)out)[(size_t)b * OUT_F4 + t] = make_float4(o0, o1, o2, o3);
    }
}

extern "C" void kernel_launch(void* const* d_in, const int* in_sizes, int n_in,
                              void* d_out, int out_size)
{
    const float* pep  = (const float*)d_in[0];
    const int*   pock = (const int*)d_in[1];
    const float* ker  = (const float*)d_in[2];
    float*       out  = (float*)d_out;

    const int B = in_sizes[1] / NPOCK;   // pocket_encoding is [B, 34]

    pep_pocket_conv_kernel<<<B, 256>>>(pep, pock, ker, out);
}